// round 1
// baseline (speedup 1.0000x reference)
#include <cuda_runtime.h>
#include <stdint.h>

#define NN 100000
#define EE 800000
#define HDIM 128

// ---------------- scratch (device globals; no allocation) ----------------
__device__ float g_inv_buf[(size_t)NN * HDIM];  // mlp_inv(feat) per node
__device__ float g_accum[(size_t)NN * HDIM];    // segment sums
__device__ float g_res[(size_t)NN * HDIM];      // mlp_and(neigh)
__device__ int   g_degc[NN];                    // degree counts

// ---------------- smem layout (floats) ----------------
// w1: [64][132] padded rows  (stride 132 -> per-8-lane-phase conflict-free LDS.128)
// w2: [64][68], w3: [128][68]
#define OFF_W1 0
#define LW1 (64 * 132)
#define OFF_B1 (OFF_W1 + LW1)          // 8448
#define OFF_W2 (OFF_B1 + 64)           // 8512
#define LW2 (64 * 68)
#define OFF_B2 (OFF_W2 + LW2)          // 12864
#define OFF_W3 (OFF_B2 + 64)           // 12928
#define LW3 (128 * 68)
#define OFF_B3 (OFF_W3 + LW3)          // 21632
#define OFF_SCR (OFF_B3 + 128)         // 21760
#define SCR_PER_WARP 192               // x[128] + y[64]
#define SMEM_FLOATS (OFF_SCR + 8 * SCR_PER_WARP)   // 23296 floats = 93184 B

__device__ __forceinline__ float lrelu(float v) {
    return v >= 0.0f ? v : 0.01f * v;
}

// PRE_DIV: divide input row by max(deg,1).  SEL_MODE: rows with sel!=1 are copied.
template <int PRE_DIV, int SEL_MODE>
__global__ void __launch_bounds__(256, 2) mlp3_kernel(
    const float* __restrict__ in, float* __restrict__ out,
    const float* __restrict__ w1, const float* __restrict__ b1,
    const float* __restrict__ w2, const float* __restrict__ b2,
    const float* __restrict__ w3, const float* __restrict__ b3,
    const int* __restrict__ deg, const int* __restrict__ sel, int nrows)
{
    extern __shared__ float s[];
    const int tid = threadIdx.x;

    // stage weights into smem (padded rows)
    for (int i = tid; i < 64 * 128; i += 256) s[OFF_W1 + (i >> 7) * 132 + (i & 127)] = w1[i];
    for (int i = tid; i < 64;       i += 256) s[OFF_B1 + i] = b1[i];
    for (int i = tid; i < 64 * 64;  i += 256) s[OFF_W2 + (i >> 6) * 68 + (i & 63)] = w2[i];
    for (int i = tid; i < 64;       i += 256) s[OFF_B2 + i] = b2[i];
    for (int i = tid; i < 128 * 64; i += 256) s[OFF_W3 + (i >> 6) * 68 + (i & 63)] = w3[i];
    for (int i = tid; i < 128;      i += 256) s[OFF_B3 + i] = b3[i];
    __syncthreads();

    const int warp = tid >> 5;
    const int lane = tid & 31;
    float* xs = s + OFF_SCR + warp * SCR_PER_WARP;  // 128 floats
    float* ys = xs + 128;                            // 64 floats

    for (int row = blockIdx.x * 8 + warp; row < nrows; row += gridDim.x * 8) {
        if (SEL_MODE) {
            if (sel[row] != 1) {  // warp-uniform: copy row through
                const float4* ip = (const float4*)(in + (size_t)row * HDIM);
                float4* op = (float4*)(out + (size_t)row * HDIM);
                op[lane] = ip[lane];
                continue;
            }
        }
        float scale = 1.0f;
        if (PRE_DIV) {
            int dg = deg[row];
            scale = 1.0f / (float)(dg < 1 ? 1 : dg);
        }
        const float* ip = in + (size_t)row * HDIM;
        xs[lane]      = ip[lane]      * scale;
        xs[lane + 32] = ip[lane + 32] * scale;
        xs[lane + 64] = ip[lane + 64] * scale;
        xs[lane + 96] = ip[lane + 96] * scale;
        __syncwarp();

        // ---- layer 1: 128 -> 64, lane owns outputs (lane, lane+32) ----
        float a0 = s[OFF_B1 + lane];
        float a1 = s[OFF_B1 + lane + 32];
        {
            const float* wa = s + OFF_W1 + lane * 132;
            const float* wb = s + OFF_W1 + (lane + 32) * 132;
            #pragma unroll
            for (int k = 0; k < 128; k += 4) {
                float4 xv = *(const float4*)(xs + k);
                float4 va = *(const float4*)(wa + k);
                float4 vb = *(const float4*)(wb + k);
                a0 = fmaf(va.x, xv.x, a0); a0 = fmaf(va.y, xv.y, a0);
                a0 = fmaf(va.z, xv.z, a0); a0 = fmaf(va.w, xv.w, a0);
                a1 = fmaf(vb.x, xv.x, a1); a1 = fmaf(vb.y, xv.y, a1);
                a1 = fmaf(vb.z, xv.z, a1); a1 = fmaf(vb.w, xv.w, a1);
            }
        }
        a0 = lrelu(a0); a1 = lrelu(a1);
        __syncwarp();                 // all lanes done reading xs
        ys[lane] = a0; ys[lane + 32] = a1;
        __syncwarp();

        // ---- layer 2: 64 -> 64 ----
        float c0 = s[OFF_B2 + lane];
        float c1 = s[OFF_B2 + lane + 32];
        {
            const float* wa = s + OFF_W2 + lane * 68;
            const float* wb = s + OFF_W2 + (lane + 32) * 68;
            #pragma unroll
            for (int k = 0; k < 64; k += 4) {
                float4 xv = *(const float4*)(ys + k);
                float4 va = *(const float4*)(wa + k);
                float4 vb = *(const float4*)(wb + k);
                c0 = fmaf(va.x, xv.x, c0); c0 = fmaf(va.y, xv.y, c0);
                c0 = fmaf(va.z, xv.z, c0); c0 = fmaf(va.w, xv.w, c0);
                c1 = fmaf(vb.x, xv.x, c1); c1 = fmaf(vb.y, xv.y, c1);
                c1 = fmaf(vb.z, xv.z, c1); c1 = fmaf(vb.w, xv.w, c1);
            }
        }
        c0 = lrelu(c0); c1 = lrelu(c1);
        __syncwarp();                 // all lanes done reading ys (and long past xs reads)
        xs[lane] = c0; xs[lane + 32] = c1;   // reuse xs[0..63] for z
        __syncwarp();

        // ---- layer 3: 64 -> 128, lane owns outputs lane + 32*i ----
        float o0 = s[OFF_B3 + lane];
        float o1 = s[OFF_B3 + lane + 32];
        float o2 = s[OFF_B3 + lane + 64];
        float o3 = s[OFF_B3 + lane + 96];
        {
            const float* w0p = s + OFF_W3 + (lane)       * 68;
            const float* w1p = s + OFF_W3 + (lane + 32)  * 68;
            const float* w2p = s + OFF_W3 + (lane + 64)  * 68;
            const float* w3p = s + OFF_W3 + (lane + 96)  * 68;
            #pragma unroll
            for (int k = 0; k < 64; k += 4) {
                float4 xv = *(const float4*)(xs + k);
                float4 v0 = *(const float4*)(w0p + k);
                float4 v1 = *(const float4*)(w1p + k);
                float4 v2 = *(const float4*)(w2p + k);
                float4 v3 = *(const float4*)(w3p + k);
                o0 = fmaf(v0.x, xv.x, o0); o0 = fmaf(v0.y, xv.y, o0);
                o0 = fmaf(v0.z, xv.z, o0); o0 = fmaf(v0.w, xv.w, o0);
                o1 = fmaf(v1.x, xv.x, o1); o1 = fmaf(v1.y, xv.y, o1);
                o1 = fmaf(v1.z, xv.z, o1); o1 = fmaf(v1.w, xv.w, o1);
                o2 = fmaf(v2.x, xv.x, o2); o2 = fmaf(v2.y, xv.y, o2);
                o2 = fmaf(v2.z, xv.z, o2); o2 = fmaf(v2.w, xv.w, o2);
                o3 = fmaf(v3.x, xv.x, o3); o3 = fmaf(v3.y, xv.y, o3);
                o3 = fmaf(v3.z, xv.z, o3); o3 = fmaf(v3.w, xv.w, o3);
            }
        }
        float* op = out + (size_t)row * HDIM;
        op[lane]      = o0;
        op[lane + 32] = o1;
        op[lane + 64] = o2;
        op[lane + 96] = o3;
        __syncwarp();                 // all lanes done reading xs before next iter overwrites
    }
}

// warp-per-edge scatter: m = (r==1 ? g_inv : feat)[src] ; atomicAdd into accum[dst]
__global__ void edge_kernel(const float* __restrict__ feat, const float* __restrict__ ginv,
                            const int* __restrict__ src, const int* __restrict__ dst,
                            const int* __restrict__ r,
                            float* __restrict__ accum, int* __restrict__ deg)
{
    int w = (blockIdx.x * blockDim.x + threadIdx.x) >> 5;
    int lane = threadIdx.x & 31;
    if (w >= EE) return;
    int sn = src[w];
    int dn = dst[w];
    const float* rowp = ((r[w] == 1) ? ginv : feat) + (size_t)sn * HDIM;
    float* arow = accum + (size_t)dn * HDIM;
    float v0 = rowp[lane];
    float v1 = rowp[lane + 32];
    float v2 = rowp[lane + 64];
    float v3 = rowp[lane + 96];
    atomicAdd(arow + lane,      v0);
    atomicAdd(arow + lane + 32, v1);
    atomicAdd(arow + lane + 64, v2);
    atomicAdd(arow + lane + 96, v3);
    if (lane == 0) atomicAdd(deg + dn, 1);
}

extern "C" void kernel_launch(void* const* d_in, const int* in_sizes, int n_in,
                              void* d_out, int out_size)
{
    const float* feat = (const float*)d_in[0];
    const int*   src  = (const int*)d_in[1];
    const int*   dst  = (const int*)d_in[2];
    const int*   r    = (const int*)d_in[3];
    const int*   inv  = (const int*)d_in[4];
    const float* iw1 = (const float*)d_in[5];
    const float* ib1 = (const float*)d_in[6];
    const float* iw2 = (const float*)d_in[7];
    const float* ib2 = (const float*)d_in[8];
    const float* iw3 = (const float*)d_in[9];
    const float* ib3 = (const float*)d_in[10];
    const float* aw1 = (const float*)d_in[11];
    const float* ab1 = (const float*)d_in[12];
    const float* aw2 = (const float*)d_in[13];
    const float* ab2 = (const float*)d_in[14];
    const float* aw3 = (const float*)d_in[15];
    const float* ab3 = (const float*)d_in[16];
    float* out = (float*)d_out;

    float *ginv, *acc, *res;
    int* deg;
    cudaGetSymbolAddress((void**)&ginv, g_inv_buf);
    cudaGetSymbolAddress((void**)&acc,  g_accum);
    cudaGetSymbolAddress((void**)&res,  g_res);
    cudaGetSymbolAddress((void**)&deg,  g_degc);

    const size_t smem = SMEM_FLOATS * sizeof(float);
    cudaFuncSetAttribute(mlp3_kernel<0, 0>, cudaFuncAttributeMaxDynamicSharedMemorySize, (int)smem);
    cudaFuncSetAttribute(mlp3_kernel<1, 0>, cudaFuncAttributeMaxDynamicSharedMemorySize, (int)smem);
    cudaFuncSetAttribute(mlp3_kernel<0, 1>, cudaFuncAttributeMaxDynamicSharedMemorySize, (int)smem);

    cudaMemsetAsync(acc, 0, (size_t)NN * HDIM * sizeof(float));
    cudaMemsetAsync(deg, 0, (size_t)NN * sizeof(int));

    // 1) g_inv = mlp_inv(feat) for all nodes
    mlp3_kernel<0, 0><<<296, 256, smem>>>(feat, ginv, iw1, ib1, iw2, ib2, iw3, ib3,
                                          nullptr, nullptr, NN);
    // 2) edge gather + scatter-add (mean numerator) + degree
    edge_kernel<<<(EE * 32 + 255) / 256, 256>>>(feat, ginv, src, dst, r, acc, deg);
    // 3) neigh = acc/deg ; res = mlp_and(neigh)
    mlp3_kernel<1, 0><<<296, 256, smem>>>(acc, res, aw1, ab1, aw2, ab2, aw3, ab3,
                                          deg, nullptr, NN);
    // 4) out = inv ? mlp_inv(res) : res
    mlp3_kernel<0, 1><<<296, 256, smem>>>(res, out, iw1, ib1, iw2, ib2, iw3, ib3,
                                          nullptr, inv, NN);
}

// round 3
// speedup vs baseline: 1.8428x; 1.8428x over previous
#include <cuda_runtime.h>
#include <stdint.h>

#define NN 100000
#define EE 800000
#define HDIM 128
#define NBLK_SCAN 98            // ceil(100000/1024)

// ---------------- scratch (device globals; no allocation) ----------------
__device__ float    g_pq[(size_t)NN * 128];   // [p(64) | q(64)] per node
__device__ float    g_sum[(size_t)NN * 64];   // aggregated 64-wide sums
__device__ unsigned g_packed[EE];             // CSR edge payload: src | (r<<31)
__device__ int      g_deg[NN];
__device__ int      g_start[NN];
__device__ int      g_cursor[NN];
__device__ int      g_bsum[NBLK_SCAN];
__device__ int      g_boff[NBLK_SCAN];
__device__ int      g_list[NN];
__device__ int      g_cnt[1];

__device__ __forceinline__ float lrelu(float v) { return v >= 0.0f ? v : 0.01f * v; }

// ================= blocked layer primitives (warp, 4 rows) =================
// weights in smem padded to stride K+4 (conflict-free per-phase LDS.128)

template <int K, bool ACT, bool BIAS>
__device__ __forceinline__ void layer64(const float* __restrict__ xs, int xstr,
                                        const float* __restrict__ W,
                                        const float* __restrict__ B,
                                        int lane, float o[4][2])
{
    const int WS = K + 4;
    const float* wa = W + lane * WS;
    const float* wb = wa + 32 * WS;
    float b0 = BIAS ? B[lane] : 0.0f;
    float b1 = BIAS ? B[lane + 32] : 0.0f;
    #pragma unroll
    for (int r = 0; r < 4; r++) { o[r][0] = b0; o[r][1] = b1; }
    #pragma unroll 4
    for (int k = 0; k < K; k += 4) {
        float4 va = *(const float4*)(wa + k);
        float4 vb = *(const float4*)(wb + k);
        #pragma unroll
        for (int r = 0; r < 4; r++) {
            float4 xv = *(const float4*)(xs + r * xstr + k);
            o[r][0] = fmaf(va.x, xv.x, o[r][0]); o[r][0] = fmaf(va.y, xv.y, o[r][0]);
            o[r][0] = fmaf(va.z, xv.z, o[r][0]); o[r][0] = fmaf(va.w, xv.w, o[r][0]);
            o[r][1] = fmaf(vb.x, xv.x, o[r][1]); o[r][1] = fmaf(vb.y, xv.y, o[r][1]);
            o[r][1] = fmaf(vb.z, xv.z, o[r][1]); o[r][1] = fmaf(vb.w, xv.w, o[r][1]);
        }
    }
    if (ACT) {
        #pragma unroll
        for (int r = 0; r < 4; r++) { o[r][0] = lrelu(o[r][0]); o[r][1] = lrelu(o[r][1]); }
    }
}

// K=64 -> 128 outputs (4 per lane)
template <bool BIAS>
__device__ __forceinline__ void layer128(const float* __restrict__ xs, int xstr,
                                         const float* __restrict__ W,
                                         const float* __restrict__ B,
                                         int lane, float o[4][4])
{
    const int WS = 68;
    const float* w0 = W + lane * WS;
    const float* w1 = w0 + 32 * WS;
    const float* w2 = w0 + 64 * WS;
    const float* w3 = w0 + 96 * WS;
    #pragma unroll
    for (int r = 0; r < 4; r++) {
        o[r][0] = BIAS ? B[lane]      : 0.0f;
        o[r][1] = BIAS ? B[lane + 32] : 0.0f;
        o[r][2] = BIAS ? B[lane + 64] : 0.0f;
        o[r][3] = BIAS ? B[lane + 96] : 0.0f;
    }
    #pragma unroll 2
    for (int k = 0; k < 64; k += 4) {
        float4 v0 = *(const float4*)(w0 + k);
        float4 v1 = *(const float4*)(w1 + k);
        float4 v2 = *(const float4*)(w2 + k);
        float4 v3 = *(const float4*)(w3 + k);
        #pragma unroll
        for (int r = 0; r < 4; r++) {
            float4 xv = *(const float4*)(xs + r * xstr + k);
            o[r][0] = fmaf(v0.x, xv.x, o[r][0]); o[r][0] = fmaf(v0.y, xv.y, o[r][0]);
            o[r][0] = fmaf(v0.z, xv.z, o[r][0]); o[r][0] = fmaf(v0.w, xv.w, o[r][0]);
            o[r][1] = fmaf(v1.x, xv.x, o[r][1]); o[r][1] = fmaf(v1.y, xv.y, o[r][1]);
            o[r][1] = fmaf(v1.z, xv.z, o[r][1]); o[r][1] = fmaf(v1.w, xv.w, o[r][1]);
            o[r][2] = fmaf(v2.x, xv.x, o[r][2]); o[r][2] = fmaf(v2.y, xv.y, o[r][2]);
            o[r][2] = fmaf(v2.z, xv.z, o[r][2]); o[r][2] = fmaf(v2.w, xv.w, o[r][2]);
            o[r][3] = fmaf(v3.x, xv.x, o[r][3]); o[r][3] = fmaf(v3.y, xv.y, o[r][3]);
            o[r][3] = fmaf(v3.z, xv.z, o[r][3]); o[r][3] = fmaf(v3.w, xv.w, o[r][3]);
        }
    }
}

// ================= k_pq: p = feat@aw1^T, g=mlp_inv(feat), q = g@aw1^T =================
// smem (floats): aw1[64*132]@0, iw1@8448, iw2[64*68]@16896, iw3[128*68]@21248,
//                ib1@29952, ib2@30016, ib3@30080, scratch@30208 (1024/warp)
#define PQ_AW1 0
#define PQ_IW1 8448
#define PQ_IW2 16896
#define PQ_IW3 21248
#define PQ_IB1 29952
#define PQ_IB2 30016
#define PQ_IB3 30080
#define PQ_SCR 30208
#define PQ_SMEM_BYTES ((PQ_SCR + 16 * 1024) * 4)

__global__ void __launch_bounds__(512, 1) k_pq(
    const float* __restrict__ feat,
    const float* __restrict__ aw1,
    const float* __restrict__ iw1, const float* __restrict__ ib1,
    const float* __restrict__ iw2, const float* __restrict__ ib2,
    const float* __restrict__ iw3, const float* __restrict__ ib3,
    float* __restrict__ pq)
{
    extern __shared__ float s[];
    const int tid = threadIdx.x;
    for (int i = tid; i < 64 * 128; i += 512) s[PQ_AW1 + (i >> 7) * 132 + (i & 127)] = aw1[i];
    for (int i = tid; i < 64 * 128; i += 512) s[PQ_IW1 + (i >> 7) * 132 + (i & 127)] = iw1[i];
    for (int i = tid; i < 64 * 64;  i += 512) s[PQ_IW2 + (i >> 6) * 68 + (i & 63)] = iw2[i];
    for (int i = tid; i < 128 * 64; i += 512) s[PQ_IW3 + (i >> 6) * 68 + (i & 63)] = iw3[i];
    for (int i = tid; i < 64;  i += 512) { s[PQ_IB1 + i] = ib1[i]; s[PQ_IB2 + i] = ib2[i]; }
    for (int i = tid; i < 128; i += 512) s[PQ_IB3 + i] = ib3[i];
    __syncthreads();

    const int warp = tid >> 5, lane = tid & 31;
    float* xbuf = s + PQ_SCR + warp * 1024;  // 4*128
    float* tbuf = xbuf + 512;                 // 4*64
    float* ubuf = tbuf + 256;                 // 4*64

    for (int base = (blockIdx.x * 16 + warp) * 4; base < NN; base += gridDim.x * 16 * 4) {
        #pragma unroll
        for (int r = 0; r < 4; r++) {
            int row = base + r; int rowc = row < NN ? row : NN - 1;
            float4 v = *(const float4*)(feat + (size_t)rowc * 128 + lane * 4);
            *(float4*)(xbuf + r * 128 + lane * 4) = v;
        }
        __syncwarp();
        // p (no bias/act), store to pq[:,0:64]
        float p[4][2];
        layer64<128, false, false>(xbuf, 128, s + PQ_AW1, nullptr, lane, p);
        #pragma unroll
        for (int r = 0; r < 4; r++) if (base + r < NN) {
            pq[(size_t)(base + r) * 128 + lane]      = p[r][0];
            pq[(size_t)(base + r) * 128 + lane + 32] = p[r][1];
        }
        // inv layer1
        float t[4][2];
        layer64<128, true, true>(xbuf, 128, s + PQ_IW1, s + PQ_IB1, lane, t);
        __syncwarp();
        #pragma unroll
        for (int r = 0; r < 4; r++) { tbuf[r * 64 + lane] = t[r][0]; tbuf[r * 64 + lane + 32] = t[r][1]; }
        __syncwarp();
        // inv layer2
        float u[4][2];
        layer64<64, true, true>(tbuf, 64, s + PQ_IW2, s + PQ_IB2, lane, u);
        __syncwarp();
        #pragma unroll
        for (int r = 0; r < 4; r++) { ubuf[r * 64 + lane] = u[r][0]; ubuf[r * 64 + lane + 32] = u[r][1]; }
        __syncwarp();
        // inv layer3 -> g (overwrite xbuf)
        float go[4][4];
        layer128<true>(ubuf, 64, s + PQ_IW3, s + PQ_IB3, lane, go);
        __syncwarp();
        #pragma unroll
        for (int r = 0; r < 4; r++) {
            xbuf[r * 128 + lane]      = go[r][0];
            xbuf[r * 128 + lane + 32] = go[r][1];
            xbuf[r * 128 + lane + 64] = go[r][2];
            xbuf[r * 128 + lane + 96] = go[r][3];
        }
        __syncwarp();
        // q = g @ aw1^T (no bias/act), store to pq[:,64:128]
        float q[4][2];
        layer64<128, false, false>(xbuf, 128, s + PQ_AW1, nullptr, lane, q);
        #pragma unroll
        for (int r = 0; r < 4; r++) if (base + r < NN) {
            pq[(size_t)(base + r) * 128 + 64 + lane]      = q[r][0];
            pq[(size_t)(base + r) * 128 + 64 + lane + 32] = q[r][1];
        }
        __syncwarp();
    }
}

// ================= CSR build =================
__global__ void k_hist(const int* __restrict__ dst, int* __restrict__ deg) {
    int i = blockIdx.x * 1024 + threadIdx.x;
    if (i < EE) atomicAdd(&deg[dst[i]], 1);
}

__global__ void k_scanA(const int* __restrict__ deg, int* __restrict__ bsum) {
    __shared__ int ws[32];
    int i = blockIdx.x * 1024 + threadIdx.x;
    int v = (i < NN) ? deg[i] : 0;
    #pragma unroll
    for (int d = 16; d > 0; d >>= 1) v += __shfl_down_sync(~0u, v, d);
    int lane = threadIdx.x & 31, wid = threadIdx.x >> 5;
    if (lane == 0) ws[wid] = v;
    __syncthreads();
    if (wid == 0) {
        int t = ws[lane];
        #pragma unroll
        for (int d = 16; d > 0; d >>= 1) t += __shfl_down_sync(~0u, t, d);
        if (lane == 0) bsum[blockIdx.x] = t;
    }
}

__global__ void k_scanB(const int* __restrict__ bsum, int* __restrict__ boff) {
    __shared__ int s[128];
    int t = threadIdx.x;
    int v = (t < NBLK_SCAN) ? bsum[t] : 0;
    s[t] = v;
    __syncthreads();
    for (int d = 1; d < 128; d <<= 1) {
        int x = (t >= d) ? s[t - d] : 0;
        __syncthreads();
        s[t] += x;
        __syncthreads();
    }
    if (t < NBLK_SCAN) boff[t] = s[t] - v;   // exclusive
}

__global__ void k_scanC(const int* __restrict__ deg, const int* __restrict__ boff,
                        int* __restrict__ start, int* __restrict__ cursor) {
    __shared__ int ws[32];
    int i = blockIdx.x * 1024 + threadIdx.x;
    int lane = threadIdx.x & 31, wid = threadIdx.x >> 5;
    int v = (i < NN) ? deg[i] : 0;
    int incl = v;
    #pragma unroll
    for (int d = 1; d < 32; d <<= 1) {
        int n = __shfl_up_sync(~0u, incl, d);
        if (lane >= d) incl += n;
    }
    if (lane == 31) ws[wid] = incl;
    __syncthreads();
    if (wid == 0) {
        int wv = ws[lane];
        int wi = wv;
        #pragma unroll
        for (int d = 1; d < 32; d <<= 1) {
            int n = __shfl_up_sync(~0u, wi, d);
            if (lane >= d) wi += n;
        }
        ws[lane] = wi - wv;   // exclusive warp offsets
    }
    __syncthreads();
    int excl = incl - v + ws[wid] + boff[blockIdx.x];
    if (i < NN) { start[i] = excl; cursor[i] = excl; }
}

__global__ void k_fill(const int* __restrict__ src, const int* __restrict__ dst,
                       const int* __restrict__ r, int* __restrict__ cursor,
                       unsigned* __restrict__ packed) {
    int i = blockIdx.x * 1024 + threadIdx.x;
    if (i >= EE) return;
    int d = dst[i];
    int pos = atomicAdd(&cursor[d], 1);
    packed[pos] = (unsigned)src[i] | ((unsigned)r[i] << 31);
}

// warp per node: sum 64-wide messages
__global__ void k_gather(const float* __restrict__ pq, const unsigned* __restrict__ packed,
                         const int* __restrict__ start, const int* __restrict__ deg,
                         float* __restrict__ sum) {
    int w = (blockIdx.x * blockDim.x + threadIdx.x) >> 5;
    int lane = threadIdx.x & 31;
    if (w >= NN) return;
    int s0 = start[w];
    int e = s0 + deg[w];
    float a0 = 0.0f, a1 = 0.0f;
    for (int j = s0; j < e; j++) {
        unsigned v = __ldg(&packed[j]);
        const float* rp = pq + (size_t)(v & 0x7FFFFFFFu) * 128 + ((v >> 31) << 6);
        a0 += rp[lane];
        a1 += rp[lane + 32];
    }
    sum[(size_t)w * 64 + lane]      = a0;
    sum[(size_t)w * 64 + lane + 32] = a1;
}

// ================= k_node: h1 = lrelu(sum/deg + ab1); l2; l3 -> out; compact inv rows =================
#define ND_AW2 0
#define ND_AW3 4352
#define ND_AB1 13056
#define ND_AB2 13120
#define ND_AB3 13184
#define ND_SCR 13312
#define ND_SMEM_BYTES ((ND_SCR + 8 * 512) * 4)

__global__ void __launch_bounds__(256, 2) k_node(
    const float* __restrict__ sum, const int* __restrict__ deg,
    const int* __restrict__ inv,
    const float* __restrict__ aw2, const float* __restrict__ ab2,
    const float* __restrict__ aw3, const float* __restrict__ ab3,
    const float* __restrict__ ab1,
    float* __restrict__ out, int* __restrict__ list, int* __restrict__ cnt)
{
    extern __shared__ float s[];
    const int tid = threadIdx.x;
    for (int i = tid; i < 64 * 64;  i += 256) s[ND_AW2 + (i >> 6) * 68 + (i & 63)] = aw2[i];
    for (int i = tid; i < 128 * 64; i += 256) s[ND_AW3 + (i >> 6) * 68 + (i & 63)] = aw3[i];
    for (int i = tid; i < 64;  i += 256) { s[ND_AB1 + i] = ab1[i]; s[ND_AB2 + i] = ab2[i]; }
    for (int i = tid; i < 128; i += 256) s[ND_AB3 + i] = ab3[i];
    __syncthreads();

    const int warp = tid >> 5, lane = tid & 31;
    float* h1buf = s + ND_SCR + warp * 512;  // 4*64
    float* h2buf = h1buf + 256;               // 4*64

    for (int base = (blockIdx.x * 8 + warp) * 4; base < NN; base += gridDim.x * 8 * 4) {
        #pragma unroll
        for (int r = 0; r < 4; r++) {
            int row = base + r; int rowc = row < NN ? row : NN - 1;
            int dg = deg[rowc];
            float scale = 1.0f / (float)(dg < 1 ? 1 : dg);
            float v0 = sum[(size_t)rowc * 64 + lane]      * scale + s[ND_AB1 + lane];
            float v1 = sum[(size_t)rowc * 64 + lane + 32] * scale + s[ND_AB1 + lane + 32];
            h1buf[r * 64 + lane]      = lrelu(v0);
            h1buf[r * 64 + lane + 32] = lrelu(v1);
        }
        __syncwarp();
        float h2[4][2];
        layer64<64, true, true>(h1buf, 64, s + ND_AW2, s + ND_AB2, lane, h2);
        __syncwarp();
        #pragma unroll
        for (int r = 0; r < 4; r++) { h2buf[r * 64 + lane] = h2[r][0]; h2buf[r * 64 + lane + 32] = h2[r][1]; }
        __syncwarp();
        float res[4][4];
        layer128<true>(h2buf, 64, s + ND_AW3, s + ND_AB3, lane, res);
        #pragma unroll
        for (int r = 0; r < 4; r++) {
            int row = base + r;
            if (row < NN) {
                float* op = out + (size_t)row * 128;
                op[lane]      = res[r][0];
                op[lane + 32] = res[r][1];
                op[lane + 64] = res[r][2];
                op[lane + 96] = res[r][3];
                if (lane == 0 && inv[row] == 1) {
                    int pos = atomicAdd(cnt, 1);
                    list[pos] = row;
                }
            }
        }
        __syncwarp();
    }
}

// ================= k_inv: mlp_inv on compacted rows (in-place on out) =================
#define IV_IW1 0
#define IV_IW2 8448
#define IV_IW3 12800
#define IV_IB1 21504
#define IV_IB2 21568
#define IV_IB3 21632
#define IV_SCR 21760
#define IV_SMEM_BYTES ((IV_SCR + 16 * 1024) * 4)

__global__ void __launch_bounds__(512, 1) k_inv(
    const float* __restrict__ iw1, const float* __restrict__ ib1,
    const float* __restrict__ iw2, const float* __restrict__ ib2,
    const float* __restrict__ iw3, const float* __restrict__ ib3,
    const int* __restrict__ list, const int* __restrict__ cnt,
    float* __restrict__ out)
{
    extern __shared__ float s[];
    const int total = *cnt;
    const int tid = threadIdx.x;
    for (int i = tid; i < 64 * 128; i += 512) s[IV_IW1 + (i >> 7) * 132 + (i & 127)] = iw1[i];
    for (int i = tid; i < 64 * 64;  i += 512) s[IV_IW2 + (i >> 6) * 68 + (i & 63)] = iw2[i];
    for (int i = tid; i < 128 * 64; i += 512) s[IV_IW3 + (i >> 6) * 68 + (i & 63)] = iw3[i];
    for (int i = tid; i < 64;  i += 512) { s[IV_IB1 + i] = ib1[i]; s[IV_IB2 + i] = ib2[i]; }
    for (int i = tid; i < 128; i += 512) s[IV_IB3 + i] = ib3[i];
    __syncthreads();
    if (total == 0) return;

    const int warp = tid >> 5, lane = tid & 31;
    float* xbuf = s + IV_SCR + warp * 1024;
    float* tbuf = xbuf + 512;
    float* ubuf = tbuf + 256;

    for (int base = (blockIdx.x * 16 + warp) * 4; base < total; base += gridDim.x * 16 * 4) {
        int rows[4];
        #pragma unroll
        for (int r = 0; r < 4; r++) {
            int idx = base + r;
            rows[r] = (idx < total) ? list[idx] : -1;
            int rowc = rows[r] >= 0 ? rows[r] : list[base];
            float4 v = *(const float4*)(out + (size_t)rowc * 128 + lane * 4);
            *(float4*)(xbuf + r * 128 + lane * 4) = v;
        }
        __syncwarp();
        float t[4][2];
        layer64<128, true, true>(xbuf, 128, s + IV_IW1, s + IV_IB1, lane, t);
        __syncwarp();
        #pragma unroll
        for (int r = 0; r < 4; r++) { tbuf[r * 64 + lane] = t[r][0]; tbuf[r * 64 + lane + 32] = t[r][1]; }
        __syncwarp();
        float u[4][2];
        layer64<64, true, true>(tbuf, 64, s + IV_IW2, s + IV_IB2, lane, u);
        __syncwarp();
        #pragma unroll
        for (int r = 0; r < 4; r++) { ubuf[r * 64 + lane] = u[r][0]; ubuf[r * 64 + lane + 32] = u[r][1]; }
        __syncwarp();
        float go[4][4];
        layer128<true>(ubuf, 64, s + IV_IW3, s + IV_IB3, lane, go);
        #pragma unroll
        for (int r = 0; r < 4; r++) {
            if (rows[r] >= 0) {
                float* op = out + (size_t)rows[r] * 128;
                op[lane]      = go[r][0];
                op[lane + 32] = go[r][1];
                op[lane + 64] = go[r][2];
                op[lane + 96] = go[r][3];
            }
        }
        __syncwarp();
    }
}

// ================= host =================
extern "C" void kernel_launch(void* const* d_in, const int* in_sizes, int n_in,
                              void* d_out, int out_size)
{
    const float* feat = (const float*)d_in[0];
    const int*   src  = (const int*)d_in[1];
    const int*   dst  = (const int*)d_in[2];
    const int*   r    = (const int*)d_in[3];
    const int*   inv  = (const int*)d_in[4];
    const float* iw1 = (const float*)d_in[5];
    const float* ib1 = (const float*)d_in[6];
    const float* iw2 = (const float*)d_in[7];
    const float* ib2 = (const float*)d_in[8];
    const float* iw3 = (const float*)d_in[9];
    const float* ib3 = (const float*)d_in[10];
    const float* aw1 = (const float*)d_in[11];
    const float* ab1 = (const float*)d_in[12];
    const float* aw2 = (const float*)d_in[13];
    const float* ab2 = (const float*)d_in[14];
    const float* aw3 = (const float*)d_in[15];
    const float* ab3 = (const float*)d_in[16];
    float* out = (float*)d_out;

    float *pq, *sum;
    unsigned* packed;
    int *deg, *start, *cursor, *bsum, *boff, *list, *cnt;
    cudaGetSymbolAddress((void**)&pq, g_pq);
    cudaGetSymbolAddress((void**)&sum, g_sum);
    cudaGetSymbolAddress((void**)&packed, g_packed);
    cudaGetSymbolAddress((void**)&deg, g_deg);
    cudaGetSymbolAddress((void**)&start, g_start);
    cudaGetSymbolAddress((void**)&cursor, g_cursor);
    cudaGetSymbolAddress((void**)&bsum, g_bsum);
    cudaGetSymbolAddress((void**)&boff, g_boff);
    cudaGetSymbolAddress((void**)&list, g_list);
    cudaGetSymbolAddress((void**)&cnt, g_cnt);

    cudaFuncSetAttribute(k_pq,   cudaFuncAttributeMaxDynamicSharedMemorySize, PQ_SMEM_BYTES);
    cudaFuncSetAttribute(k_node, cudaFuncAttributeMaxDynamicSharedMemorySize, ND_SMEM_BYTES);
    cudaFuncSetAttribute(k_inv,  cudaFuncAttributeMaxDynamicSharedMemorySize, IV_SMEM_BYTES);

    cudaMemsetAsync(deg, 0, NN * sizeof(int));
    cudaMemsetAsync(cnt, 0, sizeof(int));

    // per-node projections (dominant MLP work)
    k_pq<<<148, 512, PQ_SMEM_BYTES>>>(feat, aw1, iw1, ib1, iw2, ib2, iw3, ib3, pq);

    // CSR build (independent of k_pq output)
    k_hist<<<(EE + 1023) / 1024, 1024>>>(dst, deg);
    k_scanA<<<NBLK_SCAN, 1024>>>(deg, bsum);
    k_scanB<<<1, 128>>>(bsum, boff);
    k_scanC<<<NBLK_SCAN, 1024>>>(deg, boff, start, cursor);
    k_fill<<<(EE + 1023) / 1024, 1024>>>(src, dst, r, cursor, packed);

    // aggregate 64-wide
    k_gather<<<(NN + 7) / 8, 256>>>(pq, packed, start, deg, sum);

    // node MLP (layers 2,3 of and) + compaction of inv rows
    k_node<<<296, 256, ND_SMEM_BYTES>>>(sum, deg, inv, aw2, ab2, aw3, ab3, ab1, out, list, cnt);

    // inverter MLP on compacted rows, in-place on out
    k_inv<<<296, 512, IV_SMEM_BYTES>>>(iw1, ib1, iw2, ib2, iw3, ib3, list, cnt, out);
}

// round 5
// speedup vs baseline: 1.9305x; 1.0476x over previous
#include <cuda_runtime.h>
#include <stdint.h>

#define NN 100000
#define EE 800000
#define NBLK_SCAN 98            // ceil(100000/1024)

typedef unsigned long long ull;

// ---------------- scratch (device globals; no allocation) ----------------
__device__ float    g_g[(size_t)NN * 128];    // mlp_inv(feat) per node
__device__ float    g_sum[(size_t)NN * 128];  // aggregated 128-wide sums
__device__ unsigned g_packed[EE];             // CSR edge payload: src | (r<<31)
__device__ int      g_deg[NN];
__device__ int      g_start[NN];
__device__ int      g_cursor[NN];
__device__ int      g_bsum[NBLK_SCAN];
__device__ int      g_boff[NBLK_SCAN];
__device__ int      g_list[NN];
__device__ int      g_cnt[1];

__device__ __forceinline__ float lrelu(float v) { return v >= 0.0f ? v : 0.01f * v; }

__device__ __forceinline__ void fma2(ull &d, ull a, ull b) {
    asm("fma.rn.f32x2 %0, %1, %2, %0;" : "+l"(d) : "l"(a), "l"(b));
}
__device__ __forceinline__ ull pack2(float lo, float hi) {
    ull r; asm("mov.b64 %0, {%1, %2};" : "=l"(r) : "f"(lo), "f"(hi)); return r;
}
__device__ __forceinline__ void unpack2(ull v, float &lo, float &hi) {
    asm("mov.b64 {%0, %1}, %2;" : "=f"(lo), "=f"(hi) : "l"(v));
}

// ---------------- smem layout (shared by k_g / k_node / k_inv) ----------------
// W1d: 64 rows x 260 (dup K=128), W2d: 64 x 132 (dup K=64), W3d: 128 x 132 (dup K=64)
#define OFF_W1 0
#define OFF_W2 16640
#define OFF_W3 25088
#define OFF_B1 41984
#define OFF_B2 42048
#define OFF_B3 42112
#define OFF_SCR 42240
#define WARP_SCR 1536            // xbuf/u (1024) + tbuf (512)
#define SMEM_FLOATS (OFF_SCR + 8 * WARP_SCR)    // 54528 floats = 218112 B

// stage weights duplicated: s[o*WS + 2k] = s[o*WS + 2k + 1] = w[o*K + k]
__device__ __forceinline__ void stage_dup(float* s, const float* __restrict__ w,
                                          int OUT, int K, int WS, int tid, int nthr) {
    for (int i = tid; i < OUT * K; i += nthr) {
        int o = i / K, k = i - o * K;
        float v = w[i];
        int b = o * WS + 2 * k;
        s[b] = v; s[b + 1] = v;
    }
}

// ---- packed layer: [4 row-pairs] x K -> 64 outs, writes packed dst (stride 128/pair)
template <int K, bool ACT>
__device__ __forceinline__ void layer64p(
    const float* __restrict__ xs,   // packed pairs, stride 2K floats per pair
    const float* __restrict__ Wd,   // dup weights, stride 2K+4
    const float* __restrict__ B,
    int lane, float* __restrict__ dst)
{
    const int WS = 2 * K + 4;
    const float* wa = Wd + lane * WS;
    const float* wb = Wd + (lane + 32) * WS;
    ull bi0 = pack2(B[lane], B[lane]);
    ull bi1 = pack2(B[lane + 32], B[lane + 32]);
    ull acc0[4], acc1[4];
    #pragma unroll
    for (int p = 0; p < 4; p++) { acc0[p] = bi0; acc1[p] = bi1; }
    #pragma unroll 8
    for (int k2 = 0; k2 < 2 * K; k2 += 4) {
        ulonglong2 wva = *(const ulonglong2*)(wa + k2);
        ulonglong2 wvb = *(const ulonglong2*)(wb + k2);
        #pragma unroll
        for (int p = 0; p < 4; p++) {
            ulonglong2 xv = *(const ulonglong2*)(xs + p * 2 * K + k2);
            fma2(acc0[p], xv.x, wva.x); fma2(acc0[p], xv.y, wva.y);
            fma2(acc1[p], xv.x, wvb.x); fma2(acc1[p], xv.y, wvb.y);
        }
    }
    #pragma unroll
    for (int p = 0; p < 4; p++) {
        float lo, hi;
        unpack2(acc0[p], lo, hi);
        if (ACT) { lo = lrelu(lo); hi = lrelu(hi); }
        dst[p * 128 + 2 * lane] = lo; dst[p * 128 + 2 * lane + 1] = hi;
        unpack2(acc1[p], lo, hi);
        if (ACT) { lo = lrelu(lo); hi = lrelu(hi); }
        dst[p * 128 + 2 * (lane + 32)] = lo; dst[p * 128 + 2 * (lane + 32) + 1] = hi;
    }
}

// ---- packed layer: [4 pairs] x 64 -> 128 outs, accumulators returned packed
__device__ __forceinline__ void layer128p(
    const float* __restrict__ xs,   // packed, stride 128 per pair
    const float* __restrict__ Wd,   // 128 x 132
    const float* __restrict__ B,
    int lane, ull o[4][4])
{
    const int WS = 132;
    const float* w0 = Wd + lane * WS;
    const float* w1 = Wd + (lane + 32) * WS;
    const float* w2 = Wd + (lane + 64) * WS;
    const float* w3 = Wd + (lane + 96) * WS;
    ull b0 = pack2(B[lane], B[lane]);
    ull b1 = pack2(B[lane + 32], B[lane + 32]);
    ull b2 = pack2(B[lane + 64], B[lane + 64]);
    ull b3 = pack2(B[lane + 96], B[lane + 96]);
    #pragma unroll
    for (int p = 0; p < 4; p++) { o[p][0] = b0; o[p][1] = b1; o[p][2] = b2; o[p][3] = b3; }
    #pragma unroll 4
    for (int k2 = 0; k2 < 128; k2 += 4) {
        ulonglong2 v0 = *(const ulonglong2*)(w0 + k2);
        ulonglong2 v1 = *(const ulonglong2*)(w1 + k2);
        ulonglong2 v2 = *(const ulonglong2*)(w2 + k2);
        ulonglong2 v3 = *(const ulonglong2*)(w3 + k2);
        #pragma unroll
        for (int p = 0; p < 4; p++) {
            ulonglong2 xv = *(const ulonglong2*)(xs + p * 128 + k2);
            fma2(o[p][0], xv.x, v0.x); fma2(o[p][0], xv.y, v0.y);
            fma2(o[p][1], xv.x, v1.x); fma2(o[p][1], xv.y, v1.y);
            fma2(o[p][2], xv.x, v2.x); fma2(o[p][2], xv.y, v2.y);
            fma2(o[p][3], xv.x, v3.x); fma2(o[p][3], xv.y, v3.y);
        }
    }
}

// ================= k_g: g = mlp_inv(feat) for all nodes =================
__global__ void __launch_bounds__(256, 1) k_g(
    const float* __restrict__ feat,
    const float* __restrict__ iw1, const float* __restrict__ ib1,
    const float* __restrict__ iw2, const float* __restrict__ ib2,
    const float* __restrict__ iw3, const float* __restrict__ ib3,
    float* __restrict__ g)
{
    extern __shared__ float s[];
    const int tid = threadIdx.x;
    stage_dup(s + OFF_W1, iw1, 64, 128, 260, tid, 256);
    stage_dup(s + OFF_W2, iw2, 64, 64, 132, tid, 256);
    stage_dup(s + OFF_W3, iw3, 128, 64, 132, tid, 256);
    for (int i = tid; i < 64;  i += 256) { s[OFF_B1 + i] = ib1[i]; s[OFF_B2 + i] = ib2[i]; }
    for (int i = tid; i < 128; i += 256) s[OFF_B3 + i] = ib3[i];
    __syncthreads();

    const int warp = tid >> 5, lane = tid & 31;
    float* xbuf = s + OFF_SCR + warp * WARP_SCR;  // 1024: x (then u)
    float* tbuf = xbuf + 1024;                     // 512

    for (int base = (blockIdx.x * 8 + warp) * 8; base < NN; base += gridDim.x * 64) {
        #pragma unroll
        for (int p = 0; p < 4; p++) {
            int r0 = base + 2 * p;     if (r0 >= NN) r0 = NN - 1;
            int r1 = base + 2 * p + 1; if (r1 >= NN) r1 = NN - 1;
            float4 a = *(const float4*)(feat + (size_t)r0 * 128 + 4 * lane);
            float4 b = *(const float4*)(feat + (size_t)r1 * 128 + 4 * lane);
            *(float4*)(xbuf + p * 256 + 8 * lane)     = make_float4(a.x, b.x, a.y, b.y);
            *(float4*)(xbuf + p * 256 + 8 * lane + 4) = make_float4(a.z, b.z, a.w, b.w);
        }
        __syncwarp();
        layer64p<128, true>(xbuf, s + OFF_W1, s + OFF_B1, lane, tbuf);
        __syncwarp();
        layer64p<64, true>(tbuf, s + OFF_W2, s + OFF_B2, lane, xbuf);
        __syncwarp();
        ull o[4][4];
        layer128p(xbuf, s + OFF_W3, s + OFF_B3, lane, o);
        #pragma unroll
        for (int p = 0; p < 4; p++) {
            int r0 = base + 2 * p, r1 = r0 + 1;
            #pragma unroll
            for (int j = 0; j < 4; j++) {
                float lo, hi;
                unpack2(o[p][j], lo, hi);
                if (r0 < NN) g[(size_t)r0 * 128 + lane + 32 * j] = lo;
                if (r1 < NN) g[(size_t)r1 * 128 + lane + 32 * j] = hi;
            }
        }
        __syncwarp();
    }
}

// ================= CSR build =================
__global__ void k_hist(const int* __restrict__ dst, int* __restrict__ deg) {
    int i = blockIdx.x * 1024 + threadIdx.x;
    if (i < EE) atomicAdd(&deg[dst[i]], 1);
}

__global__ void k_scanA(const int* __restrict__ deg, int* __restrict__ bsum) {
    __shared__ int ws[32];
    int i = blockIdx.x * 1024 + threadIdx.x;
    int v = (i < NN) ? deg[i] : 0;
    #pragma unroll
    for (int d = 16; d > 0; d >>= 1) v += __shfl_down_sync(~0u, v, d);
    int lane = threadIdx.x & 31, wid = threadIdx.x >> 5;
    if (lane == 0) ws[wid] = v;
    __syncthreads();
    if (wid == 0) {
        int t = ws[lane];
        #pragma unroll
        for (int d = 16; d > 0; d >>= 1) t += __shfl_down_sync(~0u, t, d);
        if (lane == 0) bsum[blockIdx.x] = t;
    }
}

__global__ void k_scanB(const int* __restrict__ bsum, int* __restrict__ boff) {
    __shared__ int s[128];
    int t = threadIdx.x;
    int v = (t < NBLK_SCAN) ? bsum[t] : 0;
    s[t] = v;
    __syncthreads();
    for (int d = 1; d < 128; d <<= 1) {
        int x = (t >= d) ? s[t - d] : 0;
        __syncthreads();
        s[t] += x;
        __syncthreads();
    }
    if (t < NBLK_SCAN) boff[t] = s[t] - v;   // exclusive
}

__global__ void k_scanC(const int* __restrict__ deg, const int* __restrict__ boff,
                        int* __restrict__ start, int* __restrict__ cursor) {
    __shared__ int ws[32];
    int i = blockIdx.x * 1024 + threadIdx.x;
    int lane = threadIdx.x & 31, wid = threadIdx.x >> 5;
    int v = (i < NN) ? deg[i] : 0;
    int incl = v;
    #pragma unroll
    for (int d = 1; d < 32; d <<= 1) {
        int n = __shfl_up_sync(~0u, incl, d);
        if (lane >= d) incl += n;
    }
    if (lane == 31) ws[wid] = incl;
    __syncthreads();
    if (wid == 0) {
        int wv = ws[lane];
        int wi = wv;
        #pragma unroll
        for (int d = 1; d < 32; d <<= 1) {
            int n = __shfl_up_sync(~0u, wi, d);
            if (lane >= d) wi += n;
        }
        ws[lane] = wi - wv;
    }
    __syncthreads();
    int excl = incl - v + ws[wid] + boff[blockIdx.x];
    if (i < NN) { start[i] = excl; cursor[i] = excl; }
}

__global__ void k_fill(const int* __restrict__ src, const int* __restrict__ dst,
                       const int* __restrict__ r, int* __restrict__ cursor,
                       unsigned* __restrict__ packed) {
    int i = blockIdx.x * 1024 + threadIdx.x;
    if (i >= EE) return;
    int d = dst[i];
    int pos = atomicAdd(&cursor[d], 1);
    packed[pos] = (unsigned)src[i] | ((unsigned)r[i] << 31);
}

// ================= k_gather: warp per node, 128-wide sums =================
__global__ void k_gather(const float* __restrict__ feat, const float* __restrict__ g,
                         const unsigned* __restrict__ packed,
                         const int* __restrict__ start, const int* __restrict__ deg,
                         float* __restrict__ sum) {
    int w = (blockIdx.x * blockDim.x + threadIdx.x) >> 5;
    int lane = threadIdx.x & 31;
    if (w >= NN) return;
    int s0 = start[w];
    int e = s0 + deg[w];
    float4 acc = make_float4(0.f, 0.f, 0.f, 0.f);
    for (int j = s0; j < e; j++) {
        unsigned v = __ldg(&packed[j]);
        const float* rp = ((v >> 31) ? g : feat) + (size_t)(v & 0x7FFFFFFFu) * 128;
        float4 x = *(const float4*)(rp + 4 * lane);
        acc.x += x.x; acc.y += x.y; acc.z += x.z; acc.w += x.w;
    }
    *(float4*)(sum + (size_t)w * 128 + 4 * lane) = acc;
}

// ================= k_node: mean -> full and-mlp -> out; compact inv rows =================
__global__ void __launch_bounds__(256, 1) k_node(
    const float* __restrict__ sum, const int* __restrict__ deg,
    const int* __restrict__ inv,
    const float* __restrict__ aw1, const float* __restrict__ ab1,
    const float* __restrict__ aw2, const float* __restrict__ ab2,
    const float* __restrict__ aw3, const float* __restrict__ ab3,
    float* __restrict__ out, int* __restrict__ list, int* __restrict__ cnt)
{
    extern __shared__ float s[];
    const int tid = threadIdx.x;
    stage_dup(s + OFF_W1, aw1, 64, 128, 260, tid, 256);
    stage_dup(s + OFF_W2, aw2, 64, 64, 132, tid, 256);
    stage_dup(s + OFF_W3, aw3, 128, 64, 132, tid, 256);
    for (int i = tid; i < 64;  i += 256) { s[OFF_B1 + i] = ab1[i]; s[OFF_B2 + i] = ab2[i]; }
    for (int i = tid; i < 128; i += 256) s[OFF_B3 + i] = ab3[i];
    __syncthreads();

    const int warp = tid >> 5, lane = tid & 31;
    float* xbuf = s + OFF_SCR + warp * WARP_SCR;
    float* tbuf = xbuf + 1024;

    for (int base = (blockIdx.x * 8 + warp) * 8; base < NN; base += gridDim.x * 64) {
        #pragma unroll
        for (int p = 0; p < 4; p++) {
            int r0 = base + 2 * p;     if (r0 >= NN) r0 = NN - 1;
            int r1 = base + 2 * p + 1; if (r1 >= NN) r1 = NN - 1;
            int d0 = deg[r0], d1 = deg[r1];
            float s0 = 1.0f / (float)(d0 < 1 ? 1 : d0);
            float s1 = 1.0f / (float)(d1 < 1 ? 1 : d1);
            float4 a = *(const float4*)(sum + (size_t)r0 * 128 + 4 * lane);
            float4 b = *(const float4*)(sum + (size_t)r1 * 128 + 4 * lane);
            a.x *= s0; a.y *= s0; a.z *= s0; a.w *= s0;
            b.x *= s1; b.y *= s1; b.z *= s1; b.w *= s1;
            *(float4*)(xbuf + p * 256 + 8 * lane)     = make_float4(a.x, b.x, a.y, b.y);
            *(float4*)(xbuf + p * 256 + 8 * lane + 4) = make_float4(a.z, b.z, a.w, b.w);
        }
        __syncwarp();
        layer64p<128, true>(xbuf, s + OFF_W1, s + OFF_B1, lane, tbuf);
        __syncwarp();
        layer64p<64, true>(tbuf, s + OFF_W2, s + OFF_B2, lane, xbuf);
        __syncwarp();
        ull o[4][4];
        layer128p(xbuf, s + OFF_W3, s + OFF_B3, lane, o);
        #pragma unroll
        for (int p = 0; p < 4; p++) {
            int r0 = base + 2 * p, r1 = r0 + 1;
            #pragma unroll
            for (int j = 0; j < 4; j++) {
                float lo, hi;
                unpack2(o[p][j], lo, hi);
                if (r0 < NN) out[(size_t)r0 * 128 + lane + 32 * j] = lo;
                if (r1 < NN) out[(size_t)r1 * 128 + lane + 32 * j] = hi;
            }
            if (lane == 0) {
                if (r0 < NN && inv[r0] == 1) { int pos = atomicAdd(cnt, 1); list[pos] = r0; }
                if (r1 < NN && inv[r1] == 1) { int pos = atomicAdd(cnt, 1); list[pos] = r1; }
            }
        }
        __syncwarp();
    }
}

// ================= k_inv: mlp_inv on compacted rows (in-place on out) =================
__global__ void __launch_bounds__(256, 1) k_inv(
    const float* __restrict__ iw1, const float* __restrict__ ib1,
    const float* __restrict__ iw2, const float* __restrict__ ib2,
    const float* __restrict__ iw3, const float* __restrict__ ib3,
    const int* __restrict__ list, const int* __restrict__ cnt,
    float* __restrict__ out)
{
    extern __shared__ float s[];
    const int tid = threadIdx.x;
    stage_dup(s + OFF_W1, iw1, 64, 128, 260, tid, 256);
    stage_dup(s + OFF_W2, iw2, 64, 64, 132, tid, 256);
    stage_dup(s + OFF_W3, iw3, 128, 64, 132, tid, 256);
    for (int i = tid; i < 64;  i += 256) { s[OFF_B1 + i] = ib1[i]; s[OFF_B2 + i] = ib2[i]; }
    for (int i = tid; i < 128; i += 256) s[OFF_B3 + i] = ib3[i];
    __syncthreads();
    const int total = *cnt;

    const int warp = tid >> 5, lane = tid & 31;
    float* xbuf = s + OFF_SCR + warp * WARP_SCR;
    float* tbuf = xbuf + 1024;

    for (int base = (blockIdx.x * 8 + warp) * 8; base < total; base += gridDim.x * 64) {
        int rows[8];
        #pragma unroll
        for (int p = 0; p < 4; p++) {
            int i0 = base + 2 * p, i1 = i0 + 1;
            rows[2 * p]     = (i0 < total) ? list[i0] : -1;
            rows[2 * p + 1] = (i1 < total) ? list[i1] : -1;
            int rc0 = rows[2 * p]     >= 0 ? rows[2 * p]     : 0;
            int rc1 = rows[2 * p + 1] >= 0 ? rows[2 * p + 1] : 0;
            float4 a = *(const float4*)(out + (size_t)rc0 * 128 + 4 * lane);
            float4 b = *(const float4*)(out + (size_t)rc1 * 128 + 4 * lane);
            *(float4*)(xbuf + p * 256 + 8 * lane)     = make_float4(a.x, b.x, a.y, b.y);
            *(float4*)(xbuf + p * 256 + 8 * lane + 4) = make_float4(a.z, b.z, a.w, b.w);
        }
        __syncwarp();
        layer64p<128, true>(xbuf, s + OFF_W1, s + OFF_B1, lane, tbuf);
        __syncwarp();
        layer64p<64, true>(tbuf, s + OFF_W2, s + OFF_B2, lane, xbuf);
        __syncwarp();
        ull o[4][4];
        layer128p(xbuf, s + OFF_W3, s + OFF_B3, lane, o);
        #pragma unroll
        for (int p = 0; p < 4; p++) {
            int r0 = rows[2 * p], r1 = rows[2 * p + 1];
            #pragma unroll
            for (int j = 0; j < 4; j++) {
                float lo, hi;
                unpack2(o[p][j], lo, hi);
                if (r0 >= 0) out[(size_t)r0 * 128 + lane + 32 * j] = lo;
                if (r1 >= 0) out[(size_t)r1 * 128 + lane + 32 * j] = hi;
            }
        }
        __syncwarp();
    }
}

// ================= host =================
extern "C" void kernel_launch(void* const* d_in, const int* in_sizes, int n_in,
                              void* d_out, int out_size)
{
    const float* feat = (const float*)d_in[0];
    const int*   src  = (const int*)d_in[1];
    const int*   dst  = (const int*)d_in[2];
    const int*   r    = (const int*)d_in[3];
    const int*   inv  = (const int*)d_in[4];
    const float* iw1 = (const float*)d_in[5];
    const float* ib1 = (const float*)d_in[6];
    const float* iw2 = (const float*)d_in[7];
    const float* ib2 = (const float*)d_in[8];
    const float* iw3 = (const float*)d_in[9];
    const float* ib3 = (const float*)d_in[10];
    const float* aw1 = (const float*)d_in[11];
    const float* ab1 = (const float*)d_in[12];
    const float* aw2 = (const float*)d_in[13];
    const float* ab2 = (const float*)d_in[14];
    const float* aw3 = (const float*)d_in[15];
    const float* ab3 = (const float*)d_in[16];
    float* out = (float*)d_out;

    float *g, *sum;
    unsigned* packed;
    int *deg, *start, *cursor, *bsum, *boff, *list, *cnt;
    cudaGetSymbolAddress((void**)&g, g_g);
    cudaGetSymbolAddress((void**)&sum, g_sum);
    cudaGetSymbolAddress((void**)&packed, g_packed);
    cudaGetSymbolAddress((void**)&deg, g_deg);
    cudaGetSymbolAddress((void**)&start, g_start);
    cudaGetSymbolAddress((void**)&cursor, g_cursor);
    cudaGetSymbolAddress((void**)&bsum, g_bsum);
    cudaGetSymbolAddress((void**)&boff, g_boff);
    cudaGetSymbolAddress((void**)&list, g_list);
    cudaGetSymbolAddress((void**)&cnt, g_cnt);

    const size_t smem = SMEM_FLOATS * sizeof(float);
    cudaFuncSetAttribute(k_g,    cudaFuncAttributeMaxDynamicSharedMemorySize, (int)smem);
    cudaFuncSetAttribute(k_node, cudaFuncAttributeMaxDynamicSharedMemorySize, (int)smem);
    cudaFuncSetAttribute(k_inv,  cudaFuncAttributeMaxDynamicSharedMemorySize, (int)smem);

    cudaMemsetAsync(deg, 0, NN * sizeof(int));
    cudaMemsetAsync(cnt, 0, sizeof(int));

    // g = mlp_inv(feat) for all nodes (packed f32x2 math)
    k_g<<<148, 256, smem>>>(feat, iw1, ib1, iw2, ib2, iw3, ib3, g);

    // CSR build (independent of k_g output)
    k_hist<<<(EE + 1023) / 1024, 1024>>>(dst, deg);
    k_scanA<<<NBLK_SCAN, 1024>>>(deg, bsum);
    k_scanB<<<1, 128>>>(bsum, boff);
    k_scanC<<<NBLK_SCAN, 1024>>>(deg, boff, start, cursor);
    k_fill<<<(EE + 1023) / 1024, 1024>>>(src, dst, r, cursor, packed);

    // aggregate 128-wide
    k_gather<<<(NN * 32 + 255) / 256, 256>>>(feat, g, packed, start, deg, sum);

    // full and-mlp on mean + compaction of inv rows
    k_node<<<148, 256, smem>>>(sum, deg, inv, aw1, ab1, aw2, ab2, aw3, ab3, out, list, cnt);

    // inverter MLP on compacted rows, in-place on out
    k_inv<<<148, 256, smem>>>(iw1, ib1, iw2, ib2, iw3, ib3, list, cnt, out);
}